// round 3
// baseline (speedup 1.0000x reference)
#include <cuda_runtime.h>
#include <math.h>

// ---------------------------------------------------------------------------
// out[i,j,k] = trilinear(vol, T @ [i,j,k,1]) with zero outside bounds.
// R2 -> R3: warp-shuffle tap sharing. Each thread loads only the 4 "floor-k"
// taps; the 4 "ceil-k" taps come from the next lane via shfl_down (valid when
// the neighbor's (fi,fj) matches and its fk == fk+1 — true for ~93% of lanes
// with this near-identity transform). Invalid lanes fall back to predicated
// LDGs. Cuts L1 accesses/thread from ~9 to ~5.3.
// ---------------------------------------------------------------------------

#define D_DIM 256
#define H_DIM 256
#define W_DIM 256

__device__ float g_T[12];      // written by setup kernel
__constant__ float c_T[12];    // read by main kernel (c-bank)

__device__ __forceinline__ void mat4_mul(const float* A, const float* B, float* C) {
    for (int r = 0; r < 4; ++r)
        for (int c = 0; c < 4; ++c) {
            float s = 0.f;
            for (int m = 0; m < 4; ++m) s += A[r * 4 + m] * B[m * 4 + c];
            C[r * 4 + c] = s;
        }
}

__device__ void mat4_inv(const float* m, float* inv) {
    inv[0]  =  m[5]*m[10]*m[15] - m[5]*m[11]*m[14] - m[9]*m[6]*m[15] + m[9]*m[7]*m[14] + m[13]*m[6]*m[11] - m[13]*m[7]*m[10];
    inv[4]  = -m[4]*m[10]*m[15] + m[4]*m[11]*m[14] + m[8]*m[6]*m[15] - m[8]*m[7]*m[14] - m[12]*m[6]*m[11] + m[12]*m[7]*m[10];
    inv[8]  =  m[4]*m[9]*m[15]  - m[4]*m[11]*m[13] - m[8]*m[5]*m[15] + m[8]*m[7]*m[13] + m[12]*m[5]*m[11] - m[12]*m[7]*m[9];
    inv[12] = -m[4]*m[9]*m[14]  + m[4]*m[10]*m[13] + m[8]*m[5]*m[14] - m[8]*m[6]*m[13] - m[12]*m[5]*m[10] + m[12]*m[6]*m[9];
    inv[1]  = -m[1]*m[10]*m[15] + m[1]*m[11]*m[14] + m[9]*m[2]*m[15] - m[9]*m[3]*m[14] - m[13]*m[2]*m[11] + m[13]*m[3]*m[10];
    inv[5]  =  m[0]*m[10]*m[15] - m[0]*m[11]*m[14] - m[8]*m[2]*m[15] + m[8]*m[3]*m[14] + m[12]*m[2]*m[11] - m[12]*m[3]*m[10];
    inv[9]  = -m[0]*m[9]*m[15]  + m[0]*m[11]*m[13] + m[8]*m[1]*m[15] - m[8]*m[3]*m[13] - m[12]*m[1]*m[11] + m[12]*m[3]*m[9];
    inv[13] =  m[0]*m[9]*m[14]  - m[0]*m[10]*m[13] - m[8]*m[1]*m[14] + m[8]*m[2]*m[13] + m[12]*m[1]*m[10] - m[12]*m[2]*m[9];
    inv[2]  =  m[1]*m[6]*m[15]  - m[1]*m[7]*m[14]  - m[5]*m[2]*m[15] + m[5]*m[3]*m[14] + m[13]*m[2]*m[7]  - m[13]*m[3]*m[6];
    inv[6]  = -m[0]*m[6]*m[15]  + m[0]*m[7]*m[14]  + m[4]*m[2]*m[15] - m[4]*m[3]*m[14] - m[12]*m[2]*m[7]  + m[12]*m[3]*m[6];
    inv[10] =  m[0]*m[5]*m[15]  - m[0]*m[7]*m[13]  - m[4]*m[1]*m[15] + m[4]*m[3]*m[13] + m[12]*m[1]*m[7]  - m[12]*m[3]*m[5];
    inv[14] = -m[0]*m[5]*m[14]  + m[0]*m[6]*m[13]  + m[4]*m[1]*m[14] - m[4]*m[2]*m[13] - m[12]*m[1]*m[6]  + m[12]*m[2]*m[5];
    inv[3]  = -m[1]*m[6]*m[11]  + m[1]*m[7]*m[10]  + m[5]*m[2]*m[11] - m[5]*m[3]*m[10] - m[9]*m[2]*m[7]   + m[9]*m[3]*m[6];
    inv[7]  =  m[0]*m[6]*m[11]  - m[0]*m[7]*m[10]  - m[4]*m[2]*m[11] + m[4]*m[3]*m[10] + m[8]*m[2]*m[7]   - m[8]*m[3]*m[6];
    inv[11] = -m[0]*m[5]*m[11]  + m[0]*m[7]*m[9]   + m[4]*m[1]*m[11] - m[4]*m[3]*m[9]  - m[8]*m[1]*m[7]   + m[8]*m[3]*m[5];
    inv[15] =  m[0]*m[5]*m[10]  - m[0]*m[6]*m[9]   - m[4]*m[1]*m[10] + m[4]*m[2]*m[9]  + m[8]*m[1]*m[6]   - m[8]*m[2]*m[5];
    float det = m[0]*inv[0] + m[1]*inv[4] + m[2]*inv[8] + m[3]*inv[12];
    float id = 1.0f / det;
    for (int i = 0; i < 16; ++i) inv[i] *= id;
}

__global__ void compute_T_kernel(const float* __restrict__ angle,
                                 const float* __restrict__ trans,
                                 const float* __restrict__ ref_v2r,
                                 const float* __restrict__ flo_v2r,
                                 const float* __restrict__ cog) {
    if (threadIdx.x != 0 || blockIdx.x != 0) return;

    float ax = angle[0], ay = angle[1], az = angle[2];
    float cx = cosf(ax), sx = sinf(ax);
    float cy = cosf(ay), sy = sinf(ay);
    float cz = cosf(az), sz = sinf(az);

    float Rx[9] = {1, 0, 0, 0, cx, -sx, 0, sx, cx};
    float Ry[9] = {cy, 0, sy, 0, 1, 0, -sy, 0, cy};
    float Rz[9] = {cz, -sz, 0, sz, cz, 0, 0, 0, 1};
    float Rxy[9], R[9];
    for (int r = 0; r < 3; ++r)
        for (int c = 0; c < 3; ++c) {
            float s = 0.f;
            for (int m = 0; m < 3; ++m) s += Rx[r*3+m] * Ry[m*3+c];
            Rxy[r*3+c] = s;
        }
    for (int r = 0; r < 3; ++r)
        for (int c = 0; c < 3; ++c) {
            float s = 0.f;
            for (int m = 0; m < 3; ++m) s += Rxy[r*3+m] * Rz[m*3+c];
            R[r*3+c] = s;
        }

    float Tc[16]  = {1,0,0,-cog[0], 0,1,0,-cog[1], 0,0,1,-cog[2], 0,0,0,1};
    float Tci[16] = {1,0,0, cog[0], 0,1,0, cog[1], 0,0,1, cog[2], 0,0,0,1};
    float Tt[16]  = {1,0,0,trans[0], 0,1,0,trans[1], 0,0,1,trans[2], 0,0,0,1};
    float Tr[16]  = {R[0],R[1],R[2],0, R[3],R[4],R[5],0, R[6],R[7],R[8],0, 0,0,0,1};

    float tmp1[16], tmp2[16], Trig[16];
    mat4_mul(Tr, Tc, tmp1);
    mat4_mul(Tt, tmp1, tmp2);
    mat4_mul(Tci, tmp2, Trig);

    float flo_inv[16];
    mat4_inv(flo_v2r, flo_inv);

    float tmp3[16], T[16];
    mat4_mul(Trig, ref_v2r, tmp3);
    mat4_mul(flo_inv, tmp3, T);

    for (int r = 0; r < 3; ++r)
        for (int c = 0; c < 4; ++c)
            g_T[r * 4 + c] = T[r * 4 + c];
}

// ---- main kernel: 1 thread/voxel, ceil-k taps via warp shuffle ----
__global__ void __launch_bounds__(256)
warp_trilinear_kernel(const float* __restrict__ vol, float* __restrict__ out) {
    const int k = threadIdx.x;          // 0..255, lane = k & 31
    const int j = blockIdx.y;
    const int i = blockIdx.z;
    const int lane = threadIdx.x & 31;

    const float fi_in = (float)i, fj_in = (float)j, fk_in = (float)k;

    float di = fmaf(c_T[0], fi_in, fmaf(c_T[1], fj_in, fmaf(c_T[2],  fk_in, c_T[3])));
    float dj = fmaf(c_T[4], fi_in, fmaf(c_T[5], fj_in, fmaf(c_T[6],  fk_in, c_T[7])));
    float dk = fmaf(c_T[8], fi_in, fmaf(c_T[9], fj_in, fmaf(c_T[10], fk_in, c_T[11])));

    const float DM1 = 255.f, HM1 = 255.f, WM1 = 255.f;
    const bool ok = (di >= 0.f) & (di <= DM1) & (dj >= 0.f) & (dj <= HM1)
                  & (dk >= 0.f) & (dk <= WM1);

    di = fminf(fmaxf(di, 0.f), DM1);
    dj = fminf(fmaxf(dj, 0.f), HM1);
    dk = fminf(fmaxf(dk, 0.f), WM1);

    const int fi = (int)floorf(di);
    const int fj = (int)floorf(dj);
    const int fk = (int)floorf(dk);
    const int ci = min(fi + 1, D_DIM - 1);
    const int cj = min(fj + 1, H_DIM - 1);
    const int ck = min(fk + 1, W_DIM - 1);

    const float wi = di - (float)fi;
    const float wj = dj - (float)fj;
    const float wk = dk - (float)fk;

    const int base_ff = (fi * H_DIM + fj) * W_DIM;
    const int base_fc = (fi * H_DIM + cj) * W_DIM;
    const int base_cf = (ci * H_DIM + fj) * W_DIM;
    const int base_cc = (ci * H_DIM + cj) * W_DIM;

    // 4 floor-k taps (always loaded, coalesced along k)
    const float a000 = __ldg(vol + base_ff + fk);
    const float a010 = __ldg(vol + base_fc + fk);
    const float a100 = __ldg(vol + base_cf + fk);
    const float a110 = __ldg(vol + base_cc + fk);

    // neighbor-lane candidates for the ceil-k taps
    const unsigned m = 0xFFFFFFFFu;
    const float n000 = __shfl_down_sync(m, a000, 1);
    const float n010 = __shfl_down_sync(m, a010, 1);
    const float n100 = __shfl_down_sync(m, a100, 1);
    const float n110 = __shfl_down_sync(m, a110, 1);
    const int   nfi  = __shfl_down_sync(m, fi, 1);
    const int   nfj  = __shfl_down_sync(m, fj, 1);
    const int   nfk  = __shfl_down_sync(m, fk, 1);

    const bool valid = (lane < 31) & (nfi == fi) & (nfj == fj) & (nfk == fk + 1);

    // fallback loads only where the shuffle is invalid (~7% of lanes)
    const float v001 = valid ? n000 : __ldg(vol + base_ff + ck);
    const float v011 = valid ? n010 : __ldg(vol + base_fc + ck);
    const float v101 = valid ? n100 : __ldg(vol + base_cf + ck);
    const float v111 = valid ? n110 : __ldg(vol + base_cc + ck);

    const float c00 = fmaf(wk, v001 - a000, a000);
    const float c01 = fmaf(wk, v011 - a010, a010);
    const float c10 = fmaf(wk, v101 - a100, a100);
    const float c11 = fmaf(wk, v111 - a110, a110);
    const float c0  = fmaf(wj, c01 - c00, c00);
    const float c1  = fmaf(wj, c11 - c10, c10);
    float r        = fmaf(wi, c1 - c0, c0);

    r = ok ? r : 0.f;

    out[(i * H_DIM + j) * W_DIM + k] = r;
}

extern "C" void kernel_launch(void* const* d_in, const int* in_sizes, int n_in,
                              void* d_out, int out_size) {
    const float* image   = (const float*)d_in[0];
    const float* angle   = (const float*)d_in[1];
    const float* trans   = (const float*)d_in[2];
    const float* ref_v2r = (const float*)d_in[3];
    const float* flo_v2r = (const float*)d_in[4];
    const float* cog     = (const float*)d_in[5];
    float* out = (float*)d_out;

    compute_T_kernel<<<1, 1>>>(angle, trans, ref_v2r, flo_v2r, cog);

    void* g_T_addr = nullptr;
    cudaGetSymbolAddress(&g_T_addr, g_T);
    cudaMemcpyToSymbolAsync(c_T, g_T_addr, 12 * sizeof(float), 0,
                            cudaMemcpyDeviceToDevice, 0);

    dim3 block(256, 1, 1);
    dim3 grid(1, H_DIM, D_DIM);
    warp_trilinear_kernel<<<grid, block>>>(image, out);
}